// round 13
// baseline (speedup 1.0000x reference)
#include <cuda_runtime.h>
#include <math.h>
#include <stdint.h>

// Problem constants
#define BATCH 32
#define NN    1024
#define DD    128
#define ROWS  (BATCH * NN)   // 32768

// Scratch (device globals — no allocation allowed)
__device__ float g_t[ROWS * DD];
__device__ float g_m[ROWS * DD];
// A-hi, chunk-tiled: [b][mt(4)][c(32)] -> 16KB block: r(256) x 64B, unit swizzle u^((r>>1)&3)
__device__ __align__(16) uint8_t g_aht[(size_t)BATCH * 4 * 32 * 16384];   // 64MB
// m2^T, chunk-tiled: [b][c(32)] -> 16KB block: n(128) x 128B (hi u0-3 || lo u4-7), swizzle unit3^(n&7)
__device__ __align__(16) uint8_t g_m2t[(size_t)BATCH * 32 * 16384];       // 16MB
__device__ __align__(16) uint16_t g_wh[6 * DD * DD];               // weights hi [n][k]
__device__ __align__(16) uint16_t g_wl[6 * DD * DD];               // weights lo

// ---------------------------------------------------------------------------
// Helpers
// ---------------------------------------------------------------------------
__device__ __forceinline__ uint32_t smem_u32(const void* p) {
    uint32_t a;
    asm("{ .reg .u64 t; cvta.to.shared.u64 t, %1; cvt.u32.u64 %0, t; }" : "=r"(a) : "l"(p));
    return a;
}
__device__ __forceinline__ uint32_t pack_bf16x2(float v0, float v1) {
    uint32_t r;
    asm("cvt.rn.bf16x2.f32 %0, %1, %2;" : "=r"(r) : "f"(v1), "f"(v0));
    return r;
}
__device__ __forceinline__ void split2(float v0, float v1, uint32_t& h, uint32_t& l) {
    h = pack_bf16x2(v0, v1);
    float r0 = v0 - __uint_as_float(h << 16);
    float r1 = v1 - __uint_as_float(h & 0xffff0000u);
    l = pack_bf16x2(r0, r1);
}
#define CP16(dst, src) \
    asm volatile("cp.async.cg.shared.global [%0], [%1], 16;" :: "r"(dst), "l"(src) : "memory")
#define CP_COMMIT() asm volatile("cp.async.commit_group;" ::: "memory")
#define CPWAIT(n)   asm volatile("cp.async.wait_group %0;" :: "n"(n) : "memory")

#define LDSM4(r0, r1, r2, r3, addr) \
    asm volatile("ldmatrix.sync.aligned.m8n8.x4.shared.b16 {%0,%1,%2,%3}, [%4];" \
        : "=r"(r0), "=r"(r1), "=r"(r2), "=r"(r3) : "r"(addr))

// 1D bulk async copy gmem->smem with mbarrier completion (sm_90 base feature)
#define BULK(dst, src, sz, mb) \
    asm volatile("cp.async.bulk.shared::cta.global.mbarrier::complete_tx::bytes [%0], [%1], %2, [%3];" \
        :: "r"(dst), "l"(src), "r"(sz), "r"(mb) : "memory")

#define MBAR_INIT(a, c) asm volatile("mbarrier.init.shared.b64 [%0], %1;" :: "r"(a), "r"(c) : "memory")
#define MBAR_EXPECT_TX(a, b) asm volatile("mbarrier.arrive.expect_tx.shared.b64 _, [%0], %1;" :: "r"(a), "r"(b) : "memory")
#define MBAR_ARRIVE(a) asm volatile("mbarrier.arrive.shared.b64 _, [%0];" :: "r"(a) : "memory")
#define FENCE_ASYNC() asm volatile("fence.proxy.async.shared::cta;" ::: "memory")

#define MBAR_WAIT(a, ph) do { \
    uint32_t _m = (a), _p = (uint32_t)(ph), _d; \
    asm volatile("{ .reg .pred p; mbarrier.try_wait.parity.acquire.cta.shared::cta.b64 p, [%1], %2; selp.b32 %0, 1, 0, p; }" \
        : "=r"(_d) : "r"(_m), "r"(_p) : "memory"); \
    if (!_d) { \
        asm volatile("{ .reg .pred P1; WL_%=: mbarrier.try_wait.parity.acquire.cta.shared::cta.b64 P1, [%0], %1, 0x989680; @P1 bra.uni WD_%=; bra.uni WL_%=; WD_%=: }" \
            :: "r"(_m), "r"(_p) : "memory"); \
    } } while (0)

__device__ __forceinline__ void mma_bf16(float d[4], const uint32_t a[4],
                                         uint32_t b0, uint32_t b1) {
    asm volatile(
        "mma.sync.aligned.m16n8k16.row.col.f32.bf16.bf16.f32 "
        "{%0,%1,%2,%3}, {%4,%5,%6,%7}, {%8,%9}, {%0,%1,%2,%3};"
        : "+f"(d[0]), "+f"(d[1]), "+f"(d[2]), "+f"(d[3])
        : "r"(a[0]), "r"(a[1]), "r"(a[2]), "r"(a[3]), "r"(b0), "r"(b1));
}

// Composite per-row scale: logmap0(proj(expmap0(h))) = s(||h||) * h
__device__ __forceinline__ float hyp_scale(float n) {
    const float EPS  = 1e-7f;
    const float MAXN = 1.0f - 1e-5f;
    float n1 = fmaxf(n, EPS);
    float r  = tanhf(n1) / n1;
    float xn = r * n;
    float n2 = fmaxf(xn, EPS);
    float s2 = (n2 > MAXN) ? (MAXN / n2) : 1.0f;
    float x2 = s2 * xn;
    float n3 = fmaxf(x2, EPS);
    float z  = fminf(n3, 1.0f - EPS);
    float lg = atanhf(z) / n3;
    return r * s2 * lg;
}

// ---------------------------------------------------------------------------
// 3-product warp-tile MMA over merged hi/lo smem tiles.
// ---------------------------------------------------------------------------
template<int PITCH, int LOOFF, int NKS, int MI>
__device__ __forceinline__ void mma_blk(uint32_t Ab, uint32_t Bb,
                                        int wma, int wnb, int lane,
                                        float (&d)[MI][4][4]) {
    const int lg = lane >> 3;
    const int lr = lane & 7;
    const uint32_t aBase = Ab + (uint32_t)((wma * (MI * 16) + (lg & 1) * 8 + lr) * PITCH
                                           + (lg >> 1) * 16);
    const uint32_t bBase = Bb + (uint32_t)((wnb * 32 + lr) * PITCH + (lg & 1) * 16
                                           + ((lg >> 1) ? LOOFF : 0));
    #pragma unroll
    for (int ks = 0; ks < NKS; ks++) {
        const uint32_t kb = (uint32_t)ks * 32;
        uint32_t bh[4][2], bl[4][2];
        #pragma unroll
        for (int ni = 0; ni < 4; ni++)
            LDSM4(bh[ni][0], bh[ni][1], bl[ni][0], bl[ni][1],
                  bBase + ni * 8 * PITCH + kb);
        #pragma unroll
        for (int mi = 0; mi < MI; mi++) {
            uint32_t ah[4], al[4];
            LDSM4(ah[0], ah[1], ah[2], ah[3], aBase + mi * 16 * PITCH + kb);
            LDSM4(al[0], al[1], al[2], al[3], aBase + mi * 16 * PITCH + kb + LOOFF);
            #pragma unroll
            for (int ni = 0; ni < 4; ni++) {
                mma_bf16(d[mi][ni], ah, bh[ni][0], bh[ni][1]);
                mma_bf16(d[mi][ni], ah, bl[ni][0], bl[ni][1]);
                mma_bf16(d[mi][ni], al, bh[ni][0], bh[ni][1]);
            }
        }
    }
}

// ---------------------------------------------------------------------------
// One-time adjacency split -> chunk-tiled, swizzled bf16-hi blocks.
// ---------------------------------------------------------------------------
__global__ void __launch_bounds__(256) split_adj(const float* __restrict__ a,
                                                 uint8_t* __restrict__ out) {
    int t = blockIdx.x * 256 + threadIdx.x;     // 0 .. 4M-1
    int u32i = t & 127;           // k/8
    int rowg = (t >> 7) & 1023;
    int b    = t >> 17;
    const float* src = a + ((size_t)b * NN + rowg) * NN + u32i * 8;
    float4 v0 = *(const float4*)src;
    float4 v1 = *(const float4*)(src + 4);
    uint4 w = make_uint4(pack_bf16x2(v0.x, v0.y), pack_bf16x2(v0.z, v0.w),
                         pack_bf16x2(v1.x, v1.y), pack_bf16x2(v1.z, v1.w));
    int mt = rowg >> 8, r = rowg & 255, c = u32i >> 2, u = u32i & 3;
    size_t dst = (((((size_t)(b * 4 + mt)) * 32 + c) * 256 + r) * 4
                  + (u ^ ((r >> 1) & 3))) * 16;
    *(uint4*)(out + dst) = w;
}

// ---------------------------------------------------------------------------
// One-time weight split into [n][k] bf16 hi/lo.
// ---------------------------------------------------------------------------
__global__ void __launch_bounds__(256) split_weights(
    const float* __restrict__ Wemb, const float* __restrict__ Wmsg,
    const float* __restrict__ Wagg, const float* __restrict__ Wproj,
    uint16_t* __restrict__ WH, uint16_t* __restrict__ WL)
{
    int mat = blockIdx.x;
    const float* src;
    bool trans;
    switch (mat) {
        case 0:  src = Wemb;            trans = false; break;
        case 1:  src = Wmsg;            trans = true;  break;
        case 2:  src = Wagg;            trans = true;  break;
        case 3:  src = Wmsg + DD * DD;  trans = true;  break;
        case 4:  src = Wagg + DD * DD;  trans = true;  break;
        default: src = Wproj;           trans = false; break;
    }
    for (int idx = threadIdx.x; idx < DD * DD; idx += 256) {
        int n = idx >> 7, k = idx & 127;
        float v = trans ? src[k * DD + n] : src[idx];
        uint32_t p = pack_bf16x2(v, 0.f);
        uint16_t hh = (uint16_t)(p & 0xffffu);
        float r = v - __uint_as_float((uint32_t)hh << 16);
        uint32_t pl = pack_bf16x2(r, 0.f);
        WH[mat * DD * DD + idx] = hh;
        WL[mat * DD * DD + idx] = (uint16_t)(pl & 0xffffu);
    }
}

// ---------------------------------------------------------------------------
// Chain smem layout: merged hi||lo rows, pitch 528.
// ---------------------------------------------------------------------------
#define PW 528
#define XBYTES (64 * PW)
#define WBYTES (128 * PW)
#define LIN_SMEM (XBYTES + WBYTES)    // 101376 -> 2 CTAs/SM

__device__ __forceinline__ void ldgsplit_X64(const float* __restrict__ g,
                                             char* X, int tid) {
    int row = tid >> 2;
    int c0  = (tid & 3) * 32;
    const float* gp = g + (size_t)row * DD + c0;
    char* ph = X + row * PW + c0 * 2;
    char* pl = ph + 256;
    #pragma unroll
    for (int i = 0; i < 8; i++) {
        float4 v = *(const float4*)(gp + i * 4);
        uint32_t h0, l0, h1, l1;
        split2(v.x, v.y, h0, l0);
        split2(v.z, v.w, h1, l1);
        *(uint2*)(ph + i * 8) = make_uint2(h0, h1);
        *(uint2*)(pl + i * 8) = make_uint2(l0, l1);
    }
}

// cp.async a pre-split weight matrix into a [n][k] tile (256 participating threads)
__device__ __forceinline__ void cpw(const uint16_t* __restrict__ WHg,
                                    const uint16_t* __restrict__ WLg,
                                    int mat, uint32_t wbase, int tid) {
    int n = tid >> 1, half = tid & 1;
    const char* src = (const char*)((half ? WLg : WHg) + (size_t)mat * DD * DD + n * DD);
    uint32_t dst = wbase + (uint32_t)(n * PW + half * 256);
    #pragma unroll
    for (int q = 0; q < 16; q++)
        CP16(dst + q * 16, src + q * 16);
}

// m2^T tiled store: value pair (h,l) for (b, n, k..k+1)
__device__ __forceinline__ void store_m2(uint8_t* __restrict__ M2, int b, int n,
                                         int k, uint32_t h, uint32_t l) {
    int c  = k >> 5;
    int u2 = (k >> 3) & 3;
    uint8_t* p = M2 + (((size_t)(b * 32 + c)) * 128 + n) * 128;
    int w = (k & 7) * 2;
    *(uint32_t*)(p + ((u2 ^ (n & 7)) * 16) + w)       = h;
    *(uint32_t*)(p + (((4 + u2) ^ (n & 7)) * 16) + w) = l;
}

// ---------------------------------------------------------------------------
// Fused chain kernel (64-row tiles, 512 CTAs, 2 CTA/SM)
// ---------------------------------------------------------------------------
template<bool FIRST>
__global__ void __launch_bounds__(256, 2) chain_kernel(
    const float* __restrict__ X,
    const uint16_t* __restrict__ WHg, const uint16_t* __restrict__ WLg,
    int emb_mat, int w1_mat, int w2_mat,
    const float* __restrict__ bias1,
    float* __restrict__ Mout,
    uint8_t* __restrict__ M2)
{
    extern __shared__ char smem[];
    const uint32_t sX = smem_u32(smem);
    const uint32_t sW = sX + XBYTES;
    char* Xp = smem;

    const int tid = threadIdx.x, lane = tid & 31, wid = tid >> 5;
    const int wm = wid & 1, wn = wid >> 1;
    const int wm2 = wid & 3, wn2 = wid >> 2;
    const int row0 = blockIdx.x * 64;
    const int bb = row0 >> 10;
    const int rb = row0 & 1023;

    float d[2][4][4];

    if (FIRST) {
        cpw(WHg, WLg, emb_mat, sW, tid);
        CP_COMMIT();
        ldgsplit_X64(X + (size_t)row0 * DD, Xp, tid);
        CPWAIT(0);
        __syncthreads();

        #pragma unroll
        for (int i = 0; i < 2; i++)
            #pragma unroll
            for (int j = 0; j < 4; j++)
                #pragma unroll
                for (int q = 0; q < 4; q++) d[i][j][q] = 0.f;
        mma_blk<PW, 256, 8, 2>(sX, sW, wm, wn, lane, d);
        __syncthreads();

        cpw(WHg, WLg, w1_mat, sW, tid);
        CP_COMMIT();

        float* stg = (float*)Xp;
        #pragma unroll
        for (int mi = 0; mi < 2; mi++) {
            int R = wm * 32 + mi * 16 + (lane >> 2);
            #pragma unroll
            for (int ni = 0; ni < 4; ni++) {
                int C = wn * 32 + ni * 8 + (lane & 3) * 2;
                stg[R * 132 + C]           = d[mi][ni][0];
                stg[R * 132 + C + 1]       = d[mi][ni][1];
                stg[(R + 8) * 132 + C]     = d[mi][ni][2];
                stg[(R + 8) * 132 + C + 1] = d[mi][ni][3];
            }
        }
        __syncthreads();

        #pragma unroll
        for (int i = 0; i < 8; i++) {
            int rr = wid * 8 + i;
            float4 v = *(float4*)&stg[rr * 132 + lane * 4];
            float ss = v.x * v.x + v.y * v.y + v.z * v.z + v.w * v.w;
            #pragma unroll
            for (int o = 16; o > 0; o >>= 1)
                ss += __shfl_xor_sync(0xffffffffu, ss, o);
            float s = hyp_scale(sqrtf(ss));
            v.x *= s; v.y *= s; v.z *= s; v.w *= s;
            __syncwarp();
            uint32_t h0, l0, h1, l1;
            split2(v.x, v.y, h0, l0);
            split2(v.z, v.w, h1, l1);
            *(uint2*)(Xp + rr * PW + lane * 8)       = make_uint2(h0, h1);
            *(uint2*)(Xp + rr * PW + 256 + lane * 8) = make_uint2(l0, l1);
        }
        CPWAIT(0);
        __syncthreads();
    } else {
        cpw(WHg, WLg, w1_mat, sW, tid);
        CP_COMMIT();
        ldgsplit_X64(X + (size_t)row0 * DD, Xp, tid);
        CPWAIT(0);
        __syncthreads();
    }

    // GEMM1: m = t @ W1 + b1
    #pragma unroll
    for (int i = 0; i < 2; i++)
        #pragma unroll
        for (int j = 0; j < 4; j++)
            #pragma unroll
            for (int q = 0; q < 4; q++) d[i][j][q] = 0.f;
    mma_blk<PW, 256, 8, 2>(sX, sW, wm, wn, lane, d);
    __syncthreads();

    cpw(WHg, WLg, w2_mat, sW, tid);
    CP_COMMIT();

    #pragma unroll
    for (int mi = 0; mi < 2; mi++) {
        int R = wm * 32 + mi * 16 + (lane >> 2);
        #pragma unroll
        for (int ni = 0; ni < 4; ni++) {
            int C = wn * 32 + ni * 8 + (lane & 3) * 2;
            float b0 = bias1[C], b1 = bias1[C + 1];
            float v0 = d[mi][ni][0] + b0, v1 = d[mi][ni][1] + b1;
            float v2 = d[mi][ni][2] + b0, v3 = d[mi][ni][3] + b1;
            *(float2*)&Mout[(size_t)(row0 + R) * DD + C]     = make_float2(v0, v1);
            *(float2*)&Mout[(size_t)(row0 + R + 8) * DD + C] = make_float2(v2, v3);
            uint32_t h, l;
            split2(v0, v1, h, l);
            *(uint32_t*)(Xp + R * PW + C * 2)       = h;
            *(uint32_t*)(Xp + R * PW + 256 + C * 2) = l;
            split2(v2, v3, h, l);
            *(uint32_t*)(Xp + (R + 8) * PW + C * 2)       = h;
            *(uint32_t*)(Xp + (R + 8) * PW + 256 + C * 2) = l;
        }
    }
    CPWAIT(0);
    __syncthreads();

    // GEMM2: m2T[n][r] = sum_k W2n[n][k] * m[r][k]
    float e[2][4][4];
    #pragma unroll
    for (int i = 0; i < 2; i++)
        #pragma unroll
        for (int j = 0; j < 4; j++)
            #pragma unroll
            for (int q = 0; q < 4; q++) e[i][j][q] = 0.f;
    mma_blk<PW, 256, 8, 2>(sW, sX, wm2, wn2, lane, e);

    #pragma unroll
    for (int mi = 0; mi < 2; mi++) {
        int Rn = wm2 * 32 + mi * 16 + (lane >> 2);
        #pragma unroll
        for (int ni = 0; ni < 4; ni++) {
            int Cr = wn2 * 32 + ni * 8 + (lane & 3) * 2;
            uint32_t h, l;
            split2(e[mi][ni][0], e[mi][ni][1], h, l);
            store_m2(M2, bb, Rn, rb + Cr, h, l);
            split2(e[mi][ni][2], e[mi][ni][3], h, l);
            store_m2(M2, bb, Rn + 8, rb + Cr, h, l);
        }
    }
}

// ---------------------------------------------------------------------------
// Big GEMM: BM=256, 512 threads, 1 CTA/SM, cp.async.bulk, KCHUNK=64,
// 3-stage full/empty mbarrier pipeline (16 chunks, prefetch depth 2).
// FUSEP: fuse final projection into the epilogue (t never hits gmem).
// ---------------------------------------------------------------------------
#define BMA      256
#define STG      65536                 // 32KB A + 32KB B per 64-k chunk
#define NSTG     3
#define NCHUNK   16
#define TBYTES   135168                // 256 rows x 528B (fp32 staging / t-bf16 tile)
#define WOFF     TBYTES                // proj weight tile at +135168 (67584 B)
#define MBAR_OFF 202752
#define AGG_SMEM 202880

template<bool FUSEP>
__global__ void __launch_bounds__(512, 1) agg_mma(
    const uint8_t* __restrict__ AT, const uint8_t* __restrict__ BT,
    const float* __restrict__ M, const float* __restrict__ bagg,
    float* __restrict__ T,
    const uint16_t* __restrict__ WHg, const uint16_t* __restrict__ WLg,
    const float* __restrict__ bp, const float* __restrict__ mask,
    float* __restrict__ out)
{
    extern __shared__ char smem[];
    const uint32_t sb = smem_u32(smem);
    const uint32_t mb_full  = sb + MBAR_OFF;            // 3 x 8B
    const uint32_t mb_empty = sb + MBAR_OFF + 24;       // 3 x 8B
    const int tid  = threadIdx.x;
    const int lane = tid & 31;
    const int wid  = tid >> 5;          // 0..15
    const int b    = blockIdx.y;
    const int mt   = blockIdx.x;
    const int row0 = mt * BMA;
    const int wm   = wid & 3;
    const int wn   = wid >> 2;

    const uint8_t* gA = AT + ((size_t)(b * 4 + mt) * 32) * 16384;
    const uint8_t* gB = BT + ((size_t)b * 32) * 16384;

    if (tid == 0) {
        #pragma unroll
        for (int s = 0; s < NSTG; s++) {
            MBAR_INIT(mb_full + s * 8, 1);
            MBAR_INIT(mb_empty + s * 8, 16);
        }
        FENCE_ASYNC();
    }
    __syncthreads();

    auto issue = [&](int c) {
        int s = c % NSTG;
        MBAR_EXPECT_TX(mb_full + s * 8, 65536u);
        BULK(sb + (uint32_t)s * STG,         gA + (size_t)c * 32768, 32768u, mb_full + s * 8);
        BULK(sb + (uint32_t)s * STG + 32768, gB + (size_t)c * 32768, 32768u, mb_full + s * 8);
    };

    if (tid == 0) { issue(0); issue(1); }

    float d[4][4][4];
    #pragma unroll
    for (int i = 0; i < 4; i++)
        #pragma unroll
        for (int j = 0; j < 4; j++)
            #pragma unroll
            for (int q = 0; q < 4; q++) d[i][j][q] = 0.f;

    const int lg = lane >> 3, lr = lane & 7;
    const int rbase = wm * 64 + (lg & 1) * 8 + lr;
    const uint32_t swzA = (uint32_t)((rbase >> 1) & 3);
    const int nbase = wn * 32 + lr;
    const uint32_t swzB = (uint32_t)(nbase & 7);
    const uint32_t u3base = (uint32_t)((lg >> 1) * 4 + (lg & 1));

    int phf[NSTG] = {0, 0, 0};
    int phe[NSTG] = {0, 0, 0};

    for (int c = 0; c < NCHUNK; c++) {
        int s = c % NSTG;

        if (tid == 0) {
            int cn = c + 2;
            if (cn < NCHUNK) {
                int sn = cn % NSTG;
                if (cn >= NSTG) { MBAR_WAIT(mb_empty + sn * 8, phe[sn]); phe[sn] ^= 1; }
                issue(cn);
            }
        }

        MBAR_WAIT(mb_full + s * 8, phf[s]);
        phf[s] ^= 1;

        #pragma unroll
        for (int ks2 = 0; ks2 < 2; ks2++) {
            uint32_t aBase = sb + (uint32_t)s * STG + (uint32_t)ks2 * 16384;
            uint32_t bBase = sb + (uint32_t)s * STG + 32768 + (uint32_t)ks2 * 16384;
            #pragma unroll
            for (int ks = 0; ks < 2; ks++) {
                uint32_t bh[4][2], bl[4][2];
                const uint32_t ub = ((u3base + ks * 2) ^ swzB) * 16;
                #pragma unroll
                for (int ni = 0; ni < 4; ni++)
                    LDSM4(bh[ni][0], bh[ni][1], bl[ni][0], bl[ni][1],
                          bBase + (uint32_t)(nbase + ni * 8) * 128 + ub);
                const uint32_t ua = (((uint32_t)(ks * 2 + (lg >> 1))) ^ swzA) * 16;
                #pragma unroll
                for (int mi = 0; mi < 4; mi++) {
                    uint32_t ah[4];
                    LDSM4(ah[0], ah[1], ah[2], ah[3],
                          aBase + (uint32_t)(rbase + mi * 16) * 64 + ua);
                    #pragma unroll
                    for (int ni = 0; ni < 4; ni++) {
                        mma_bf16(d[mi][ni], ah, bh[ni][0], bh[ni][1]);
                        mma_bf16(d[mi][ni], ah, bl[ni][0], bl[ni][1]);
                    }
                }
            }
        }

        if (lane == 0) MBAR_ARRIVE(mb_empty + s * 8);
    }
    __syncthreads();                    // all warps done; safe to reuse smem

    // stage D to smem (f32, pitch 132 floats = 528 B, 256 rows)
    float* stg = (float*)smem;
    #pragma unroll
    for (int mi = 0; mi < 4; mi++) {
        int R = wm * 64 + mi * 16 + (lane >> 2);
        #pragma unroll
        for (int ni = 0; ni < 4; ni++) {
            int C = wn * 32 + ni * 8 + (lane & 3) * 2;
            *(float2*)&stg[R * 132 + C]       = make_float2(d[mi][ni][0], d[mi][ni][1]);
            *(float2*)&stg[(R + 8) * 132 + C] = make_float2(d[mi][ni][2], d[mi][ni][3]);
        }
    }
    __syncthreads();

    if (FUSEP && tid < 256) cpw(WHg, WLg, 5, sb + WOFF, tid);   // prefetch Wproj
    if (FUSEP) CP_COMMIT();

    const float* Mb = M + ((size_t)b * NN + row0) * DD;
    float4 bg = *(const float4*)&bagg[lane * 4];
    #pragma unroll
    for (int i = 0; i < 16; i++) {
        int rr = wid * 16 + i;
        float4 raw = *(const float4*)&stg[rr * 132 + lane * 4];
        float4 mm  = *(const float4*)&Mb[(size_t)rr * DD + lane * 4];
        float v0 = fmaxf(raw.x + mm.x + bg.x, 0.f);
        float v1 = fmaxf(raw.y + mm.y + bg.y, 0.f);
        float v2 = fmaxf(raw.z + mm.z + bg.z, 0.f);
        float v3 = fmaxf(raw.w + mm.w + bg.w, 0.f);
        float ss = v0*v0 + v1*v1 + v2*v2 + v3*v3;
        #pragma unroll
        for (int o = 16; o > 0; o >>= 1)
            ss += __shfl_xor_sync(0xffffffffu, ss, o);
        float s = hyp_scale(sqrtf(ss));
        v0 *= s; v1 *= s; v2 *= s; v3 *= s;
        if (!FUSEP) {
            float* Tb = T + ((size_t)b * NN + row0) * DD;
            *(float4*)&Tb[(size_t)rr * DD + lane * 4] = make_float4(v0, v1, v2, v3);
        } else {
            // in-place resplit: whole row read by this warp before writes
            __syncwarp();
            uint32_t h0, l0, h1, l1;
            split2(v0, v1, h0, l0);
            split2(v2, v3, h1, l1);
            *(uint2*)(smem + rr * PW + lane * 8)       = make_uint2(h0, h1);
            *(uint2*)(smem + rr * PW + 256 + lane * 8) = make_uint2(l0, l1);
        }
    }

    if (FUSEP) {
        CPWAIT(0);
        __syncthreads();
        // proj GEMM: out = (t @ WprojT + bp) * mask;  A = t tile (256 rows)
        float e[4][4][4];
        #pragma unroll
        for (int i = 0; i < 4; i++)
            #pragma unroll
            for (int j = 0; j < 4; j++)
                #pragma unroll
                for (int q = 0; q < 4; q++) e[i][j][q] = 0.f;
        mma_blk<PW, 256, 8, 4>(sb, sb + WOFF, wm, wn, lane, e);

        #pragma unroll
        for (int mi = 0; mi < 4; mi++) {
            int R = wm * 64 + mi * 16 + (lane >> 2);
            float mk0 = mask[(size_t)b * NN + row0 + R];
            float mk1 = mask[(size_t)b * NN + row0 + R + 8];
            #pragma unroll
            for (int ni = 0; ni < 4; ni++) {
                int C = wn * 32 + ni * 8 + (lane & 3) * 2;
                float b0 = bp[C], b1 = bp[C + 1];
                size_t o0 = ((size_t)b * NN + row0 + R) * DD + C;
                *(float2*)&out[o0] =
                    make_float2((e[mi][ni][0] + b0) * mk0, (e[mi][ni][1] + b1) * mk0);
                *(float2*)&out[o0 + 8 * DD] =
                    make_float2((e[mi][ni][2] + b0) * mk1, (e[mi][ni][3] + b1) * mk1);
            }
        }
    }
}

// ---------------------------------------------------------------------------
// Host launch: fork-join graph.
//   side stream: split_adj                     (pure DRAM bandwidth)
//   main stream: split_weights -> chain0       (tensor/latency bound)
//   join -> agg1 -> chain1 -> agg2(fused proj)
// ---------------------------------------------------------------------------
extern "C" void kernel_launch(void* const* d_in, const int* in_sizes, int n_in,
                              void* d_out, int out_size)
{
    const float* nf    = (const float*)d_in[0];
    const float* adj   = (const float*)d_in[1];
    const float* mask  = (const float*)d_in[2];
    const float* Wemb  = (const float*)d_in[3];
    const float* Wmsg  = (const float*)d_in[4];
    const float* bmsg  = (const float*)d_in[5];
    const float* Wagg  = (const float*)d_in[6];
    const float* bagg  = (const float*)d_in[7];
    const float* Wproj = (const float*)d_in[8];
    const float* bproj = (const float*)d_in[9];
    float* out = (float*)d_out;

    float *t, *m;
    uint8_t *aht, *m2t;
    uint16_t *wh, *wl;
    cudaGetSymbolAddress((void**)&t,   g_t);
    cudaGetSymbolAddress((void**)&m,   g_m);
    cudaGetSymbolAddress((void**)&aht, g_aht);
    cudaGetSymbolAddress((void**)&m2t, g_m2t);
    cudaGetSymbolAddress((void**)&wh,  g_wh);
    cudaGetSymbolAddress((void**)&wl,  g_wl);

    static cudaStream_t s_side = nullptr;
    static cudaEvent_t ev_fork = nullptr, ev_join = nullptr;
    if (!s_side) {
        cudaStreamCreateWithFlags(&s_side, cudaStreamNonBlocking);
        cudaEventCreateWithFlags(&ev_fork, cudaEventDisableTiming);
        cudaEventCreateWithFlags(&ev_join, cudaEventDisableTiming);
        cudaFuncSetAttribute(agg_mma<false>, cudaFuncAttributeMaxDynamicSharedMemorySize, AGG_SMEM);
        cudaFuncSetAttribute(agg_mma<true>,  cudaFuncAttributeMaxDynamicSharedMemorySize, AGG_SMEM);
        cudaFuncSetAttribute(chain_kernel<true>,  cudaFuncAttributeMaxDynamicSharedMemorySize, LIN_SMEM);
        cudaFuncSetAttribute(chain_kernel<false>, cudaFuncAttributeMaxDynamicSharedMemorySize, LIN_SMEM);
    }

    dim3 glin(ROWS / 64);          // 512
    dim3 gbig(NN / BMA, BATCH);    // 4 x 32 = 128

    // fork: side branch does the adjacency split concurrently with chain0
    cudaEventRecord(ev_fork, 0);
    cudaStreamWaitEvent(s_side, ev_fork, 0);
    split_adj<<<(BATCH * NN * (NN / 8)) / 256, 256, 0, s_side>>>(adj, aht);
    cudaEventRecord(ev_join, s_side);

    // main branch
    split_weights<<<6, 256>>>(Wemb, Wmsg, Wagg, Wproj, wh, wl);
    chain_kernel<true><<<glin, 256, LIN_SMEM>>>(nf, wh, wl, 0, 1, 2,
                                                bmsg, m, m2t);

    // join before agg1 (first consumer of aht)
    cudaStreamWaitEvent(0, ev_join, 0);

    agg_mma<false><<<gbig, 512, AGG_SMEM>>>(aht, m2t, m, bagg, t,
                                            nullptr, nullptr, nullptr, nullptr, nullptr);

    // layer 1: msg + m2 fused; agg2 fuses the final projection
    chain_kernel<false><<<glin, 256, LIN_SMEM>>>(t, wh, wl, 0, 3, 4,
                                                 bmsg + DD, m, m2t);
    agg_mma<true><<<gbig, 512, AGG_SMEM>>>(aht, m2t, m, bagg + DD, nullptr,
                                           wh, wl, bproj, mask, out);
}

// round 14
// speedup vs baseline: 1.0593x; 1.0593x over previous
#include <cuda_runtime.h>
#include <math.h>
#include <stdint.h>

// Problem constants
#define BATCH 32
#define NN    1024
#define DD    128
#define ROWS  (BATCH * NN)   // 32768

// Scratch (device globals — no allocation allowed)
__device__ float g_m[ROWS * DD];
// A-hi, chunk-tiled: [b][mt(4)][c(32)] -> 16KB block: r(256) x 64B, unit swizzle u^((r>>1)&3)
__device__ __align__(16) uint8_t g_aht[(size_t)BATCH * 4 * 32 * 16384];   // 64MB
// m2^T, chunk-tiled: [b][c(32)] -> 16KB block: n(128) x 128B (hi u0-3 || lo u4-7), swizzle unit3^(n&7)
__device__ __align__(16) uint8_t g_m2t[(size_t)BATCH * 32 * 16384];       // 16MB
__device__ __align__(16) uint16_t g_wh[6 * DD * DD];               // weights hi [n][k]
__device__ __align__(16) uint16_t g_wl[6 * DD * DD];               // weights lo

// ---------------------------------------------------------------------------
// Helpers
// ---------------------------------------------------------------------------
__device__ __forceinline__ uint32_t smem_u32(const void* p) {
    uint32_t a;
    asm("{ .reg .u64 t; cvta.to.shared.u64 t, %1; cvt.u32.u64 %0, t; }" : "=r"(a) : "l"(p));
    return a;
}
__device__ __forceinline__ uint32_t pack_bf16x2(float v0, float v1) {
    uint32_t r;
    asm("cvt.rn.bf16x2.f32 %0, %1, %2;" : "=r"(r) : "f"(v1), "f"(v0));
    return r;
}
__device__ __forceinline__ void split2(float v0, float v1, uint32_t& h, uint32_t& l) {
    h = pack_bf16x2(v0, v1);
    float r0 = v0 - __uint_as_float(h << 16);
    float r1 = v1 - __uint_as_float(h & 0xffff0000u);
    l = pack_bf16x2(r0, r1);
}
#define CP16(dst, src) \
    asm volatile("cp.async.cg.shared.global [%0], [%1], 16;" :: "r"(dst), "l"(src) : "memory")
#define CP_COMMIT() asm volatile("cp.async.commit_group;" ::: "memory")
#define CPWAIT(n)   asm volatile("cp.async.wait_group %0;" :: "n"(n) : "memory")

#define LDSM4(r0, r1, r2, r3, addr) \
    asm volatile("ldmatrix.sync.aligned.m8n8.x4.shared.b16 {%0,%1,%2,%3}, [%4];" \
        : "=r"(r0), "=r"(r1), "=r"(r2), "=r"(r3) : "r"(addr))

// 1D bulk async copy gmem->smem with mbarrier completion (sm_90 base feature)
#define BULK(dst, src, sz, mb) \
    asm volatile("cp.async.bulk.shared::cta.global.mbarrier::complete_tx::bytes [%0], [%1], %2, [%3];" \
        :: "r"(dst), "l"(src), "r"(sz), "r"(mb) : "memory")

#define MBAR_INIT(a, c) asm volatile("mbarrier.init.shared.b64 [%0], %1;" :: "r"(a), "r"(c) : "memory")
#define MBAR_EXPECT_TX(a, b) asm volatile("mbarrier.arrive.expect_tx.shared.b64 _, [%0], %1;" :: "r"(a), "r"(b) : "memory")
#define MBAR_ARRIVE(a) asm volatile("mbarrier.arrive.shared.b64 _, [%0];" :: "r"(a) : "memory")
#define FENCE_ASYNC() asm volatile("fence.proxy.async.shared::cta;" ::: "memory")

#define MBAR_WAIT(a, ph) do { \
    uint32_t _m = (a), _p = (uint32_t)(ph), _d; \
    asm volatile("{ .reg .pred p; mbarrier.try_wait.parity.acquire.cta.shared::cta.b64 p, [%1], %2; selp.b32 %0, 1, 0, p; }" \
        : "=r"(_d) : "r"(_m), "r"(_p) : "memory"); \
    if (!_d) { \
        asm volatile("{ .reg .pred P1; WL_%=: mbarrier.try_wait.parity.acquire.cta.shared::cta.b64 P1, [%0], %1, 0x989680; @P1 bra.uni WD_%=; bra.uni WL_%=; WD_%=: }" \
            :: "r"(_m), "r"(_p) : "memory"); \
    } } while (0)

__device__ __forceinline__ void mma_bf16(float d[4], const uint32_t a[4],
                                         uint32_t b0, uint32_t b1) {
    asm volatile(
        "mma.sync.aligned.m16n8k16.row.col.f32.bf16.bf16.f32 "
        "{%0,%1,%2,%3}, {%4,%5,%6,%7}, {%8,%9}, {%0,%1,%2,%3};"
        : "+f"(d[0]), "+f"(d[1]), "+f"(d[2]), "+f"(d[3])
        : "r"(a[0]), "r"(a[1]), "r"(a[2]), "r"(a[3]), "r"(b0), "r"(b1));
}

// Composite per-row scale: logmap0(proj(expmap0(h))) = s(||h||) * h
__device__ __forceinline__ float hyp_scale(float n) {
    const float EPS  = 1e-7f;
    const float MAXN = 1.0f - 1e-5f;
    float n1 = fmaxf(n, EPS);
    float r  = tanhf(n1) / n1;
    float xn = r * n;
    float n2 = fmaxf(xn, EPS);
    float s2 = (n2 > MAXN) ? (MAXN / n2) : 1.0f;
    float x2 = s2 * xn;
    float n3 = fmaxf(x2, EPS);
    float z  = fminf(n3, 1.0f - EPS);
    float lg = atanhf(z) / n3;
    return r * s2 * lg;
}

// ---------------------------------------------------------------------------
// 3-product warp-tile MMA over merged hi/lo smem tiles.
// ---------------------------------------------------------------------------
template<int PITCH, int LOOFF, int NKS, int MI>
__device__ __forceinline__ void mma_blk(uint32_t Ab, uint32_t Bb,
                                        int wma, int wnb, int lane,
                                        float (&d)[MI][4][4]) {
    const int lg = lane >> 3;
    const int lr = lane & 7;
    const uint32_t aBase = Ab + (uint32_t)((wma * (MI * 16) + (lg & 1) * 8 + lr) * PITCH
                                           + (lg >> 1) * 16);
    const uint32_t bBase = Bb + (uint32_t)((wnb * 32 + lr) * PITCH + (lg & 1) * 16
                                           + ((lg >> 1) ? LOOFF : 0));
    #pragma unroll
    for (int ks = 0; ks < NKS; ks++) {
        const uint32_t kb = (uint32_t)ks * 32;
        uint32_t bh[4][2], bl[4][2];
        #pragma unroll
        for (int ni = 0; ni < 4; ni++)
            LDSM4(bh[ni][0], bh[ni][1], bl[ni][0], bl[ni][1],
                  bBase + ni * 8 * PITCH + kb);
        #pragma unroll
        for (int mi = 0; mi < MI; mi++) {
            uint32_t ah[4], al[4];
            LDSM4(ah[0], ah[1], ah[2], ah[3], aBase + mi * 16 * PITCH + kb);
            LDSM4(al[0], al[1], al[2], al[3], aBase + mi * 16 * PITCH + kb + LOOFF);
            #pragma unroll
            for (int ni = 0; ni < 4; ni++) {
                mma_bf16(d[mi][ni], ah, bh[ni][0], bh[ni][1]);
                mma_bf16(d[mi][ni], ah, bl[ni][0], bl[ni][1]);
                mma_bf16(d[mi][ni], al, bh[ni][0], bh[ni][1]);
            }
        }
    }
}
#define ZERO4(d) { _Pragma("unroll") for (int _i = 0; _i < 4; _i++) \
    _Pragma("unroll") for (int _j = 0; _j < 4; _j++) \
    _Pragma("unroll") for (int _q = 0; _q < 4; _q++) (d)[_i][_j][_q] = 0.f; }

// ---------------------------------------------------------------------------
// One-time adjacency split -> chunk-tiled, swizzled bf16-hi blocks.
// ---------------------------------------------------------------------------
__global__ void __launch_bounds__(256) split_adj(const float* __restrict__ a,
                                                 uint8_t* __restrict__ out) {
    int t = blockIdx.x * 256 + threadIdx.x;     // 0 .. 4M-1
    int u32i = t & 127;           // k/8
    int rowg = (t >> 7) & 1023;
    int b    = t >> 17;
    const float* src = a + ((size_t)b * NN + rowg) * NN + u32i * 8;
    float4 v0 = *(const float4*)src;
    float4 v1 = *(const float4*)(src + 4);
    uint4 w = make_uint4(pack_bf16x2(v0.x, v0.y), pack_bf16x2(v0.z, v0.w),
                         pack_bf16x2(v1.x, v1.y), pack_bf16x2(v1.z, v1.w));
    int mt = rowg >> 8, r = rowg & 255, c = u32i >> 2, u = u32i & 3;
    size_t dst = (((((size_t)(b * 4 + mt)) * 32 + c) * 256 + r) * 4
                  + (u ^ ((r >> 1) & 3))) * 16;
    *(uint4*)(out + dst) = w;
}

// ---------------------------------------------------------------------------
// One-time weight split into [n][k] bf16 hi/lo.
// ---------------------------------------------------------------------------
__global__ void __launch_bounds__(256) split_weights(
    const float* __restrict__ Wemb, const float* __restrict__ Wmsg,
    const float* __restrict__ Wagg, const float* __restrict__ Wproj,
    uint16_t* __restrict__ WH, uint16_t* __restrict__ WL)
{
    int mat = blockIdx.x;
    const float* src;
    bool trans;
    switch (mat) {
        case 0:  src = Wemb;            trans = false; break;
        case 1:  src = Wmsg;            trans = true;  break;
        case 2:  src = Wagg;            trans = true;  break;
        case 3:  src = Wmsg + DD * DD;  trans = true;  break;
        case 4:  src = Wagg + DD * DD;  trans = true;  break;
        default: src = Wproj;           trans = false; break;
    }
    for (int idx = threadIdx.x; idx < DD * DD; idx += 256) {
        int n = idx >> 7, k = idx & 127;
        float v = trans ? src[k * DD + n] : src[idx];
        uint32_t p = pack_bf16x2(v, 0.f);
        uint16_t hh = (uint16_t)(p & 0xffffu);
        float r = v - __uint_as_float((uint32_t)hh << 16);
        uint32_t pl = pack_bf16x2(r, 0.f);
        WH[mat * DD * DD + idx] = hh;
        WL[mat * DD * DD + idx] = (uint16_t)(pl & 0xffffu);
    }
}

// ---------------------------------------------------------------------------
// Shared tile helpers: merged hi||lo rows, pitch 528.
// ---------------------------------------------------------------------------
#define PW 528
#define XBYTES (64 * PW)
#define WBYTES (128 * PW)
#define LIN_SMEM (XBYTES + WBYTES)    // 101376 -> 2 CTAs/SM

__device__ __forceinline__ void ldgsplit_X64(const float* __restrict__ g,
                                             char* X, int tid) {
    int row = tid >> 2;
    int c0  = (tid & 3) * 32;
    const float* gp = g + (size_t)row * DD + c0;
    char* ph = X + row * PW + c0 * 2;
    char* pl = ph + 256;
    #pragma unroll
    for (int i = 0; i < 8; i++) {
        float4 v = *(const float4*)(gp + i * 4);
        uint32_t h0, l0, h1, l1;
        split2(v.x, v.y, h0, l0);
        split2(v.z, v.w, h1, l1);
        *(uint2*)(ph + i * 8) = make_uint2(h0, h1);
        *(uint2*)(pl + i * 8) = make_uint2(l0, l1);
    }
}

// cp.async a pre-split weight matrix into a [n][k] tile (256 participating threads)
__device__ __forceinline__ void cpw(const uint16_t* __restrict__ WHg,
                                    const uint16_t* __restrict__ WLg,
                                    int mat, uint32_t wbase, int tid) {
    int n = tid >> 1, half = tid & 1;
    const char* src = (const char*)((half ? WLg : WHg) + (size_t)mat * DD * DD + n * DD);
    uint32_t dst = wbase + (uint32_t)(n * PW + half * 256);
    #pragma unroll
    for (int q = 0; q < 16; q++)
        CP16(dst + q * 16, src + q * 16);
}

// m2^T tiled store: value pair (h,l) for (b, n, k..k+1)
__device__ __forceinline__ void store_m2(uint8_t* __restrict__ M2, int b, int n,
                                         int k, uint32_t h, uint32_t l) {
    int c  = k >> 5;
    int u2 = (k >> 3) & 3;
    uint8_t* p = M2 + (((size_t)(b * 32 + c)) * 128 + n) * 128;
    int w = (k & 7) * 2;
    *(uint32_t*)(p + ((u2 ^ (n & 7)) * 16) + w)       = h;
    *(uint32_t*)(p + (((4 + u2) ^ (n & 7)) * 16) + w) = l;
}

// ---------------------------------------------------------------------------
// Layer-0 chain kernel (embed + hyp + msg + m2), 64-row tiles, 2 CTA/SM
// ---------------------------------------------------------------------------
__global__ void __launch_bounds__(256, 2) chain_kernel(
    const float* __restrict__ X,
    const uint16_t* __restrict__ WHg, const uint16_t* __restrict__ WLg,
    const float* __restrict__ bias1,
    float* __restrict__ Mout,
    uint8_t* __restrict__ M2)
{
    extern __shared__ char smem[];
    const uint32_t sX = smem_u32(smem);
    const uint32_t sW = sX + XBYTES;
    char* Xp = smem;

    const int tid = threadIdx.x, lane = tid & 31, wid = tid >> 5;
    const int wm = wid & 1, wn = wid >> 1;
    const int wm2 = wid & 3, wn2 = wid >> 2;
    const int row0 = blockIdx.x * 64;
    const int bb = row0 >> 10;
    const int rb = row0 & 1023;

    float d[2][4][4];

    // GEMM0: h = nf @ Wemb^T ; t = hyp_rows(h) kept in smem
    cpw(WHg, WLg, 0, sW, tid);
    CP_COMMIT();
    ldgsplit_X64(X + (size_t)row0 * DD, Xp, tid);
    CPWAIT(0);
    __syncthreads();

    #pragma unroll
    for (int i = 0; i < 2; i++)
        #pragma unroll
        for (int j = 0; j < 4; j++)
            #pragma unroll
            for (int q = 0; q < 4; q++) d[i][j][q] = 0.f;
    mma_blk<PW, 256, 8, 2>(sX, sW, wm, wn, lane, d);
    __syncthreads();

    cpw(WHg, WLg, 1, sW, tid);
    CP_COMMIT();

    float* stg = (float*)Xp;
    #pragma unroll
    for (int mi = 0; mi < 2; mi++) {
        int R = wm * 32 + mi * 16 + (lane >> 2);
        #pragma unroll
        for (int ni = 0; ni < 4; ni++) {
            int C = wn * 32 + ni * 8 + (lane & 3) * 2;
            stg[R * 132 + C]           = d[mi][ni][0];
            stg[R * 132 + C + 1]       = d[mi][ni][1];
            stg[(R + 8) * 132 + C]     = d[mi][ni][2];
            stg[(R + 8) * 132 + C + 1] = d[mi][ni][3];
        }
    }
    __syncthreads();

    #pragma unroll
    for (int i = 0; i < 8; i++) {
        int rr = wid * 8 + i;
        float4 v = *(float4*)&stg[rr * 132 + lane * 4];
        float ss = v.x * v.x + v.y * v.y + v.z * v.z + v.w * v.w;
        #pragma unroll
        for (int o = 16; o > 0; o >>= 1)
            ss += __shfl_xor_sync(0xffffffffu, ss, o);
        float s = hyp_scale(sqrtf(ss));
        v.x *= s; v.y *= s; v.z *= s; v.w *= s;
        __syncwarp();
        uint32_t h0, l0, h1, l1;
        split2(v.x, v.y, h0, l0);
        split2(v.z, v.w, h1, l1);
        *(uint2*)(Xp + rr * PW + lane * 8)       = make_uint2(h0, h1);
        *(uint2*)(Xp + rr * PW + 256 + lane * 8) = make_uint2(l0, l1);
    }
    CPWAIT(0);
    __syncthreads();

    // GEMM1: m = t @ W1 + b1
    #pragma unroll
    for (int i = 0; i < 2; i++)
        #pragma unroll
        for (int j = 0; j < 4; j++)
            #pragma unroll
            for (int q = 0; q < 4; q++) d[i][j][q] = 0.f;
    mma_blk<PW, 256, 8, 2>(sX, sW, wm, wn, lane, d);
    __syncthreads();

    cpw(WHg, WLg, 2, sW, tid);
    CP_COMMIT();

    #pragma unroll
    for (int mi = 0; mi < 2; mi++) {
        int R = wm * 32 + mi * 16 + (lane >> 2);
        #pragma unroll
        for (int ni = 0; ni < 4; ni++) {
            int C = wn * 32 + ni * 8 + (lane & 3) * 2;
            float b0 = bias1[C], b1 = bias1[C + 1];
            float v0 = d[mi][ni][0] + b0, v1 = d[mi][ni][1] + b1;
            float v2 = d[mi][ni][2] + b0, v3 = d[mi][ni][3] + b1;
            *(float2*)&Mout[(size_t)(row0 + R) * DD + C]     = make_float2(v0, v1);
            *(float2*)&Mout[(size_t)(row0 + R + 8) * DD + C] = make_float2(v2, v3);
            uint32_t h, l;
            split2(v0, v1, h, l);
            *(uint32_t*)(Xp + R * PW + C * 2)       = h;
            *(uint32_t*)(Xp + R * PW + 256 + C * 2) = l;
            split2(v2, v3, h, l);
            *(uint32_t*)(Xp + (R + 8) * PW + C * 2)       = h;
            *(uint32_t*)(Xp + (R + 8) * PW + 256 + C * 2) = l;
        }
    }
    CPWAIT(0);
    __syncthreads();

    // GEMM2: m2T[n][r] = sum_k W2n[n][k] * m[r][k]
    float e[2][4][4];
    #pragma unroll
    for (int i = 0; i < 2; i++)
        #pragma unroll
        for (int j = 0; j < 4; j++)
            #pragma unroll
            for (int q = 0; q < 4; q++) e[i][j][q] = 0.f;
    mma_blk<PW, 256, 8, 2>(sW, sX, wm2, wn2, lane, e);

    #pragma unroll
    for (int mi = 0; mi < 2; mi++) {
        int Rn = wm2 * 32 + mi * 16 + (lane >> 2);
        #pragma unroll
        for (int ni = 0; ni < 4; ni++) {
            int Cr = wn2 * 32 + ni * 8 + (lane & 3) * 2;
            uint32_t h, l;
            split2(e[mi][ni][0], e[mi][ni][1], h, l);
            store_m2(M2, bb, Rn, rb + Cr, h, l);
            split2(e[mi][ni][2], e[mi][ni][3], h, l);
            store_m2(M2, bb, Rn + 8, rb + Cr, h, l);
        }
    }
}

// ---------------------------------------------------------------------------
// Big GEMM: BM=256, 512 threads, 1 CTA/SM, cp.async.bulk, KCHUNK=64,
// 3-stage full/empty mbarrier pipeline.
//   MODE 1: fused layer chain — t -> m=t@W1+b1 (gmem+smem) -> m2T=W2^T@m^T
//   MODE 2: fused projection  — t -> out = (t@WprojT + bp) * mask
// t never touches gmem in either mode.
// ---------------------------------------------------------------------------
#define BMA      256
#define STG      65536                 // 32KB A + 32KB B per 64-k chunk
#define NSTG     3
#define NCHUNK   16
#define TBYTES   135168                // 256 rows x 528B (fp32 staging / bf16 tile)
#define WOFF     TBYTES                // weight tile at +135168 (67584 B)
#define MBAR_OFF 202752
#define AGG_SMEM 202880

template<int MODE>
__global__ void __launch_bounds__(512, 1) agg_mma(
    const uint8_t* __restrict__ AT, const uint8_t* __restrict__ BT,
    const float* __restrict__ M, const float* __restrict__ bagg,
    const uint16_t* __restrict__ WHg, const uint16_t* __restrict__ WLg,
    const float* __restrict__ bvec, const float* __restrict__ mask,
    float* __restrict__ outF, uint8_t* __restrict__ M2)
{
    extern __shared__ char smem[];
    const uint32_t sb = smem_u32(smem);
    const uint32_t mb_full  = sb + MBAR_OFF;
    const uint32_t mb_empty = sb + MBAR_OFF + 24;
    const int tid  = threadIdx.x;
    const int lane = tid & 31;
    const int wid  = tid >> 5;          // 0..15
    const int b    = blockIdx.y;
    const int mt   = blockIdx.x;
    const int row0 = mt * BMA;
    const int wm   = wid & 3;
    const int wn   = wid >> 2;

    const uint8_t* gA = AT + ((size_t)(b * 4 + mt) * 32) * 16384;
    const uint8_t* gB = BT + ((size_t)b * 32) * 16384;

    if (tid == 0) {
        #pragma unroll
        for (int s = 0; s < NSTG; s++) {
            MBAR_INIT(mb_full + s * 8, 1);
            MBAR_INIT(mb_empty + s * 8, 16);
        }
        FENCE_ASYNC();
    }
    __syncthreads();

    auto issue = [&](int c) {
        int s = c % NSTG;
        MBAR_EXPECT_TX(mb_full + s * 8, 65536u);
        BULK(sb + (uint32_t)s * STG,         gA + (size_t)c * 32768, 32768u, mb_full + s * 8);
        BULK(sb + (uint32_t)s * STG + 32768, gB + (size_t)c * 32768, 32768u, mb_full + s * 8);
    };

    if (tid == 0) { issue(0); issue(1); }

    float d[4][4][4];
    ZERO4(d);

    const int lg = lane >> 3, lr = lane & 7;
    const int rbase = wm * 64 + (lg & 1) * 8 + lr;
    const uint32_t swzA = (uint32_t)((rbase >> 1) & 3);
    const int nbase = wn * 32 + lr;
    const uint32_t swzB = (uint32_t)(nbase & 7);
    const uint32_t u3base = (uint32_t)((lg >> 1) * 4 + (lg & 1));

    int phf[NSTG] = {0, 0, 0};
    int phe[NSTG] = {0, 0, 0};

    for (int c = 0; c < NCHUNK; c++) {
        int s = c % NSTG;

        if (tid == 0) {
            int cn = c + 2;
            if (cn < NCHUNK) {
                int sn = cn % NSTG;
                if (cn >= NSTG) { MBAR_WAIT(mb_empty + sn * 8, phe[sn]); phe[sn] ^= 1; }
                issue(cn);
            }
        }

        MBAR_WAIT(mb_full + s * 8, phf[s]);
        phf[s] ^= 1;

        #pragma unroll
        for (int ks2 = 0; ks2 < 2; ks2++) {
            uint32_t aBase = sb + (uint32_t)s * STG + (uint32_t)ks2 * 16384;
            uint32_t bBase = sb + (uint32_t)s * STG + 32768 + (uint32_t)ks2 * 16384;
            #pragma unroll
            for (int ks = 0; ks < 2; ks++) {
                uint32_t bh[4][2], bl[4][2];
                const uint32_t ub = ((u3base + ks * 2) ^ swzB) * 16;
                #pragma unroll
                for (int ni = 0; ni < 4; ni++)
                    LDSM4(bh[ni][0], bh[ni][1], bl[ni][0], bl[ni][1],
                          bBase + (uint32_t)(nbase + ni * 8) * 128 + ub);
                const uint32_t ua = (((uint32_t)(ks * 2 + (lg >> 1))) ^ swzA) * 16;
                #pragma unroll
                for (int mi = 0; mi < 4; mi++) {
                    uint32_t ah[4];
                    LDSM4(ah[0], ah[1], ah[2], ah[3],
                          aBase + (uint32_t)(rbase + mi * 16) * 64 + ua);
                    #pragma unroll
                    for (int ni = 0; ni < 4; ni++) {
                        mma_bf16(d[mi][ni], ah, bh[ni][0], bh[ni][1]);
                        mma_bf16(d[mi][ni], ah, bl[ni][0], bl[ni][1]);
                    }
                }
            }
        }

        if (lane == 0) MBAR_ARRIVE(mb_empty + s * 8);
    }
    __syncthreads();                    // all warps done; safe to reuse smem

    // stage D to smem (f32, pitch 132 floats = 528 B, 256 rows)
    float* stg = (float*)smem;
    #pragma unroll
    for (int mi = 0; mi < 4; mi++) {
        int R = wm * 64 + mi * 16 + (lane >> 2);
        #pragma unroll
        for (int ni = 0; ni < 4; ni++) {
            int C = wn * 32 + ni * 8 + (lane & 3) * 2;
            *(float2*)&stg[R * 132 + C]       = make_float2(d[mi][ni][0], d[mi][ni][1]);
            *(float2*)&stg[(R + 8) * 132 + C] = make_float2(d[mi][ni][2], d[mi][ni][3]);
        }
    }
    __syncthreads();

    // prefetch first epilogue weight: MODE 1 -> msg1 (mat 3); MODE 2 -> proj (mat 5)
    if (tid < 256) cpw(WHg, WLg, MODE == 1 ? 3 : 5, sb + WOFF, tid);
    CP_COMMIT();

    // t-row pass: relu(m + D + bagg) -> hyp rescale -> bf16 split in place
    const float* Mb = M + ((size_t)b * NN + row0) * DD;
    float4 bg = *(const float4*)&bagg[lane * 4];
    #pragma unroll
    for (int i = 0; i < 16; i++) {
        int rr = wid * 16 + i;
        float4 raw = *(const float4*)&stg[rr * 132 + lane * 4];
        float4 mm  = *(const float4*)&Mb[(size_t)rr * DD + lane * 4];
        float v0 = fmaxf(raw.x + mm.x + bg.x, 0.f);
        float v1 = fmaxf(raw.y + mm.y + bg.y, 0.f);
        float v2 = fmaxf(raw.z + mm.z + bg.z, 0.f);
        float v3 = fmaxf(raw.w + mm.w + bg.w, 0.f);
        float ss = v0*v0 + v1*v1 + v2*v2 + v3*v3;
        #pragma unroll
        for (int o = 16; o > 0; o >>= 1)
            ss += __shfl_xor_sync(0xffffffffu, ss, o);
        float s = hyp_scale(sqrtf(ss));
        v0 *= s; v1 *= s; v2 *= s; v3 *= s;
        __syncwarp();
        uint32_t h0, l0, h1, l1;
        split2(v0, v1, h0, l0);
        split2(v2, v3, h1, l1);
        *(uint2*)(smem + rr * PW + lane * 8)       = make_uint2(h0, h1);
        *(uint2*)(smem + rr * PW + 256 + lane * 8) = make_uint2(l0, l1);
    }
    CPWAIT(0);
    __syncthreads();

    // GEMM-A: t(256) @ W^T -> fragments (M=256, N=128)
    float e[4][4][4];
    ZERO4(e);
    mma_blk<PW, 256, 8, 4>(sb, sb + WOFF, wm, wn, lane, e);

    if (MODE == 2) {
        // out = (t @ WprojT + bp) * mask
        #pragma unroll
        for (int mi = 0; mi < 4; mi++) {
            int R = wm * 64 + mi * 16 + (lane >> 2);
            float mk0 = mask[(size_t)b * NN + row0 + R];
            float mk1 = mask[(size_t)b * NN + row0 + R + 8];
            #pragma unroll
            for (int ni = 0; ni < 4; ni++) {
                int C = wn * 32 + ni * 8 + (lane & 3) * 2;
                float b0 = bvec[C], b1 = bvec[C + 1];
                size_t o0 = ((size_t)b * NN + row0 + R) * DD + C;
                *(float2*)&outF[o0] =
                    make_float2((e[mi][ni][0] + b0) * mk0, (e[mi][ni][1] + b1) * mk0);
                *(float2*)&outF[o0 + 8 * DD] =
                    make_float2((e[mi][ni][2] + b0) * mk1, (e[mi][ni][3] + b1) * mk1);
            }
        }
        return;
    }

    // MODE 1: m = t@W1 + b1, write gmem + resplit into t tile, then m2T
    __syncthreads();                               // all t reads complete
    if (tid < 256) cpw(WHg, WLg, 4, sb + WOFF, tid);   // prefetch W_agg1
    CP_COMMIT();

    #pragma unroll
    for (int mi = 0; mi < 4; mi++) {
        int R = wm * 64 + mi * 16 + (lane >> 2);
        #pragma unroll
        for (int ni = 0; ni < 4; ni++) {
            int C = wn * 32 + ni * 8 + (lane & 3) * 2;
            float b0 = bvec[C], b1 = bvec[C + 1];
            float v0 = e[mi][ni][0] + b0, v1 = e[mi][ni][1] + b1;
            float v2 = e[mi][ni][2] + b0, v3 = e[mi][ni][3] + b1;
            size_t o0 = ((size_t)b * NN + row0 + R) * DD + C;
            *(float2*)&outF[o0]          = make_float2(v0, v1);
            *(float2*)&outF[o0 + 8 * DD] = make_float2(v2, v3);
            uint32_t h, l;
            split2(v0, v1, h, l);
            *(uint32_t*)(smem + R * PW + C * 2)       = h;
            *(uint32_t*)(smem + R * PW + 256 + C * 2) = l;
            split2(v2, v3, h, l);
            *(uint32_t*)(smem + (R + 8) * PW + C * 2)       = h;
            *(uint32_t*)(smem + (R + 8) * PW + 256 + C * 2) = l;
        }
    }
    CPWAIT(0);
    __syncthreads();

    // GEMM-B: m2T[n][r] = sum_k W2n[n][k] * m[r][k]   (M=128, N=256)
    const int wm2 = wid & 1, wn2 = wid >> 1;
    float f[4][4][4];
    ZERO4(f);
    mma_blk<PW, 256, 8, 4>(sb + WOFF, sb, wm2, wn2, lane, f);

    #pragma unroll
    for (int mi = 0; mi < 4; mi++) {
        int Rn = wm2 * 64 + mi * 16 + (lane >> 2);
        #pragma unroll
        for (int ni = 0; ni < 4; ni++) {
            int Cr = wn2 * 32 + ni * 8 + (lane & 3) * 2;
            uint32_t h, l;
            split2(f[mi][ni][0], f[mi][ni][1], h, l);
            store_m2(M2, b, Rn, row0 + Cr, h, l);
            split2(f[mi][ni][2], f[mi][ni][3], h, l);
            store_m2(M2, b, Rn + 8, row0 + Cr, h, l);
        }
    }
}

// ---------------------------------------------------------------------------
// Host launch
// ---------------------------------------------------------------------------
extern "C" void kernel_launch(void* const* d_in, const int* in_sizes, int n_in,
                              void* d_out, int out_size)
{
    const float* nf    = (const float*)d_in[0];
    const float* adj   = (const float*)d_in[1];
    const float* mask  = (const float*)d_in[2];
    const float* Wemb  = (const float*)d_in[3];
    const float* Wmsg  = (const float*)d_in[4];
    const float* bmsg  = (const float*)d_in[5];
    const float* Wagg  = (const float*)d_in[6];
    const float* bagg  = (const float*)d_in[7];
    const float* Wproj = (const float*)d_in[8];
    const float* bproj = (const float*)d_in[9];
    float* out = (float*)d_out;

    float *m;
    uint8_t *aht, *m2t;
    uint16_t *wh, *wl;
    cudaGetSymbolAddress((void**)&m,   g_m);
    cudaGetSymbolAddress((void**)&aht, g_aht);
    cudaGetSymbolAddress((void**)&m2t, g_m2t);
    cudaGetSymbolAddress((void**)&wh,  g_wh);
    cudaGetSymbolAddress((void**)&wl,  g_wl);

    static cudaStream_t s_side = nullptr;
    static cudaEvent_t ev_fork = nullptr, ev_join = nullptr;
    if (!s_side) {
        cudaStreamCreateWithFlags(&s_side, cudaStreamNonBlocking);
        cudaEventCreateWithFlags(&ev_fork, cudaEventDisableTiming);
        cudaEventCreateWithFlags(&ev_join, cudaEventDisableTiming);
        cudaFuncSetAttribute(agg_mma<1>, cudaFuncAttributeMaxDynamicSharedMemorySize, AGG_SMEM);
        cudaFuncSetAttribute(agg_mma<2>, cudaFuncAttributeMaxDynamicSharedMemorySize, AGG_SMEM);
        cudaFuncSetAttribute(chain_kernel, cudaFuncAttributeMaxDynamicSharedMemorySize, LIN_SMEM);
    }

    dim3 glin(ROWS / 64);          // 512
    dim3 gbig(NN / BMA, BATCH);    // 4 x 32 = 128

    // fork: adjacency split on side stream
    cudaEventRecord(ev_fork, 0);
    cudaStreamWaitEvent(s_side, ev_fork, 0);
    split_adj<<<(BATCH * NN * (NN / 8)) / 256, 256, 0, s_side>>>(adj, aht);
    cudaEventRecord(ev_join, s_side);

    // main: weights + layer-0 chain
    split_weights<<<6, 256>>>(Wemb, Wmsg, Wagg, Wproj, wh, wl);
    chain_kernel<<<glin, 256, LIN_SMEM>>>(nf, wh, wl, bmsg, m, m2t);

    cudaStreamWaitEvent(0, ev_join, 0);

    // agg1: A@m2_0 -> t -> m = t@Wmsg1 + b -> m2T_1   (chain1 fused)
    agg_mma<1><<<gbig, 512, AGG_SMEM>>>(aht, m2t, m, bagg,
                                        wh, wl, bmsg + DD, nullptr, m, m2t);

    // agg2: A@m2_1 -> t -> out = (t@WprojT + bproj) * mask
    agg_mma<2><<<gbig, 512, AGG_SMEM>>>(aht, m2t, m, bagg + DD,
                                        wh, wl, bproj, mask, out, nullptr);
}